// round 12
// baseline (speedup 1.0000x reference)
#include <cuda_runtime.h>
#include <cuda_bf16.h>
#include <cstdint>
#include <cstddef>

#define TST 192
#define BAT 256
#define HID 512
#define G4  2048
#define RWS (TST*BAT)

__device__ __nv_bfloat16 g_X[(size_t)RWS*64];
__device__ float g_XZ[(size_t)RWS*G4];
__device__ unsigned g_H1p[(size_t)TST*32*BAT*8]; // packed h1 per step [t][kb][b][8]
__device__ __nv_bfloat16 g_H2[(size_t)RWS*HID];
__device__ unsigned g_Hb1[2][32*BAT*8];
__device__ unsigned g_Hb2[2][32*BAT*8];
__device__ unsigned g_Wk1p[32*G4];
__device__ volatile unsigned g_sync[4096];

__device__ __forceinline__ unsigned pk2(float x, float y){
    __nv_bfloat162 t=__floats2bfloat162_rn(x,y);
    return *(unsigned*)&t;
}
__device__ __forceinline__ void mma16(float* d, unsigned a0,unsigned a1,unsigned a2,
                                      unsigned a3, unsigned b0,unsigned b1){
    asm volatile("mma.sync.aligned.m16n8k16.row.col.f32.bf16.bf16.f32 "
        "{%0,%1,%2,%3}, {%4,%5,%6,%7}, {%8,%9}, {%0,%1,%2,%3};\n"
        : "+f"(d[0]),"+f"(d[1]),"+f"(d[2]),"+f"(d[3])
        : "r"(a0),"r"(a1),"r"(a2),"r"(a3),"r"(b0),"r"(b1));
}
__device__ __forceinline__ unsigned su32(const void* p){
    return (unsigned)__cvta_generic_to_shared(p);
}
__device__ __forceinline__ void cp16(unsigned dst, const void* src){
    asm volatile("cp.async.cg.shared.global [%0], [%1], 16;" :: "r"(dst), "l"(src));
}
__device__ __forceinline__ void cpc(){ asm volatile("cp.async.commit_group;"); }
template<int N> __device__ __forceinline__ void cpw(){
    asm volatile("cp.async.wait_group %0;" :: "n"(N));
}
__device__ __forceinline__ void barwg(int id){
    asm volatile("bar.sync %0, 128;" :: "r"(id) : "memory");
}
__device__ __forceinline__ float tanha(float x){
    float r; asm("tanh.approx.f32 %0,%1;" : "=f"(r) : "f"(x)); return r;
}
__device__ __forceinline__ float siga(float x){ return fmaf(tanha(x*0.5f),0.5f,0.5f); }

// ---------------- prep ----------------
__global__ void prep_k(const float* __restrict__ xc, const int* __restrict__ c0,
                       const int* __restrict__ c1, const float* __restrict__ e0,
                       const float* __restrict__ e1, const float* __restrict__ Wk1){
    const size_t N1=(size_t)RWS*64, NT=N1+32*G4;
    for(size_t i=(size_t)blockIdx.x*blockDim.x+threadIdx.x; i<NT;
        i+=(size_t)gridDim.x*blockDim.x){
        if(i<N1){
            int r=(int)(i>>6), cc=(int)(i&63), t=r>>8, b=r&255;
            float v=0.f;
            if(cc<8)       v=xc[(b*TST+t)*8+cc];
            else if(cc<40) v=e0[(size_t)c0[b*TST+t]*32+(cc-8)];
            else if(cc<56) v=e1[(size_t)c1[b*TST+t]*16+(cc-40)];
            g_X[i]=__float2bfloat16_rn(v);
        } else {
            size_t j=i-N1; int jr=(int)(j>>11), n=(int)(j&2047);
            float v0=(2*jr<56)?   Wk1[(size_t)(2*jr)*G4+n]   : 0.f;
            float v1=(2*jr+1<56)? Wk1[(size_t)(2*jr+1)*G4+n] : 0.f;
            g_Wk1p[j]=pk2(v0,v1);
        }
    }
}

__global__ void zero_k(){
    int i=blockIdx.x*blockDim.x+threadIdx.x;
    if(i<131072) ((unsigned*)g_Hb1)[i]=0u;
    else if(i<262144) ((unsigned*)g_Hb2)[i-131072]=0u;
}

__global__ void rst_k(){
    if(threadIdx.x<128) g_sync[threadIdx.x*32]=0u;
}

// ---------------- GEMM1: xz1 = X@Wk1 + b1 (K=64) ----------------
__global__ __launch_bounds__(128) void gemm64(const __nv_bfloat16* __restrict__ A,
        const unsigned* __restrict__ Wp, const float* __restrict__ bias,
        float* __restrict__ C, int K){
    extern __shared__ float sm[];
    const int tid=threadIdx.x, l=tid&31, w=tid>>5, wm=w>>1, wn=w&1;
    const int g=l>>2, tg=l&3;
    const int row0=blockIdx.y*64, col0=blockIdx.x*64;
    float acc[2][4][4];
#pragma unroll
    for(int m=0;m<2;m++) for(int n=0;n<4;n++) for(int q=0;q<4;q++) acc[m][n][q]=0.f;
    const int NC=K>>6;
    auto issue=[&](int c){
        unsigned* Au=(unsigned*)(sm+(c&1)*4608);
        unsigned* Bu=Au+2304;
#pragma unroll
        for(int q=0;q<4;q++){ int e=tid+128*q, r=e>>3, s=e&7;
            cp16(su32(Au+r*36+s*4), A+(size_t)(row0+r)*K + c*64 + s*8); }
#pragma unroll
        for(int q=0;q<4;q++){ int e=tid+128*q, j=e>>4, s=e&15;
            cp16(su32(Bu+j*72+s*4), Wp+(size_t)(c*32+j)*G4 + col0 + s*4); }
    };
    issue(0); cpc();
    for(int c=0;c<NC;c++){
        if(c+1<NC){ issue(c+1); cpc(); cpw<1>(); } else cpw<0>();
        __syncthreads();
        const unsigned* Au=(const unsigned*)(sm+(c&1)*4608);
        const unsigned* Bu=Au+2304;
#pragma unroll
        for(int kb=0;kb<4;kb++){
            unsigned a[2][4];
#pragma unroll
            for(int mt=0;mt<2;mt++){
                int r=wm*32+mt*16+g;
                a[mt][0]=Au[r*36+kb*8+tg];   a[mt][1]=Au[(r+8)*36+kb*8+tg];
                a[mt][2]=Au[r*36+kb*8+tg+4]; a[mt][3]=Au[(r+8)*36+kb*8+tg+4];
            }
#pragma unroll
            for(int nt=0;nt<4;nt++){
                int cc=wn*32+nt*8+g;
                unsigned b0=Bu[(kb*8+tg)*72+cc], b1=Bu[(kb*8+tg+4)*72+cc];
                mma16(acc[0][nt],a[0][0],a[0][1],a[0][2],a[0][3],b0,b1);
                mma16(acc[1][nt],a[1][0],a[1][1],a[1][2],a[1][3],b0,b1);
            }
        }
        __syncthreads();
    }
#pragma unroll
    for(int nt=0;nt<4;nt++){
        int cc=col0+wn*32+nt*8+tg*2;
        float bx=bias[cc], by=bias[cc+1];
#pragma unroll
        for(int mt=0;mt<2;mt++){
            int r=row0+wm*32+mt*16+g;
            float2 v0={acc[mt][nt][0]+bx, acc[mt][nt][1]+by};
            float2 v1={acc[mt][nt][2]+bx, acc[mt][nt][3]+by};
            *(float2*)&C[(size_t)r*G4+cc]=v0;
            *(float2*)&C[(size_t)(r+8)*G4+cc]=v1;
        }
    }
}

// ---------------- unified persistent LSTM ----------------
// KBW = kb16 blocks per wg. SEC: K=1024=[h1(t);h2(t-1)] (gemm2 folded in).
// SMEM: Wpk (NKB*2KB) | per-wg 3x2KB stage bufs. Red reuses stages:
//   SEC red = buf1+buf2 (stg+2048), L1 red = buf0+buf1 (stg).
template<int KBW, bool SEC>
__global__ __launch_bounds__(512) void lstm_t(const float* __restrict__ xz,
        const float* __restrict__ W0, const float* __restrict__ W1,
        const float* __restrict__ bias, unsigned base){
    extern __shared__ float sm[];
    constexpr int NKB=4*KBW, C=KBW/4;
    constexpr int RED= SEC? 2048 : 0;
    uint2* Wpk=(uint2*)sm;
    float* stgb=sm+NKB*512;
    const int tid=threadIdx.x, l=tid&31, w=tid>>5;
    const int wg=w>>2, wl=w&3, wm=wl>>1, wn=wl&1;
    const int g=l>>2, tg=l&3;
    const int wtid=tid&127;
    const int strip=blockIdx.x&31, bg=blockIdx.x>>5;
    const int barid=wg+1;
    float* stg=stgb+wg*6144;

    for(int e=tid;e<NKB*256;e+=512){
        int tg_=e&3, ci=(e>>2)&63, kb=e>>8;
        int nt=ci>>4, wn_=(ci>>3)&1, gg=ci&7;
        int gcol=nt*HID+strip*16+wn_*8+gg;
        const float* W=W0; int kk=kb;
        if(SEC&&kb>=32){ W=W1; kk=kb-32; }
        int k0=kk*16+tg_*2;
        uint2 v;
        v.x=pk2(W[(size_t)k0*G4+gcol],     W[(size_t)(k0+1)*G4+gcol]);
        v.y=pk2(W[(size_t)(k0+8)*G4+gcol], W[(size_t)(k0+9)*G4+gcol]);
        Wpk[e]=v;
    }
    __syncthreads();

    float cst[2][4];
#pragma unroll
    for(int m=0;m<2;m++) for(int q=0;q<4;q++) cst[m][q]=0.f;
    float xzp[2][4][4];
    float bz[4][2];

    auto pfxz=[&](int tt){
        const float* xr=xz+(size_t)tt*BAT*G4;
#pragma unroll
        for(int mt=0;mt<2;mt++)
#pragma unroll
            for(int nt=0;nt<4;nt++){
                int b=bg*64+wm*32+mt*16+g;
                int cc=nt*HID+strip*16+wn*8+tg*2;
                float2 v0=*(const float2*)&xr[(size_t)b*G4+cc];
                float2 v1=*(const float2*)&xr[(size_t)(b+8)*G4+cc];
                xzp[mt][nt][0]=v0.x; xzp[mt][nt][1]=v0.y;
                xzp[mt][nt][2]=v1.x; xzp[mt][nt][3]=v1.y;
            }
    };
    if(wg==1){
        if(!SEC) pfxz(0);
        else {
#pragma unroll
            for(int nt=0;nt<4;nt++){
                int cc=nt*HID+strip*16+wn*8+tg*2;
                bz[nt][0]=bias[cc]; bz[nt][1]=bias[cc+1];
            }
        }
    }

    auto kbgOf=[&](int c,int kbl){
        int x=c*4+kbl;
        return SEC? ((x<8)? wg*8+x : 32+wg*8+(x-8)) : wg*8+x;
    };
    auto issueA=[&](int t,int c){
        float* dst=stg+(c%3)*2048;
        const unsigned* hb1=g_Hb1[t&1];
        const unsigned* hb2=g_Hb2[t&1];
#pragma unroll
        for(int q=0;q<4;q++){
            int e=wtid+128*q;
            int kbl=e>>7, rem=e&127, r=rem>>1, hf=rem&1;
            int kbg=kbgOf(c,kbl);
            const unsigned* src; size_t off;
            if(!SEC){ src=hb1; off=(size_t)kbg*BAT; }
            else if(kbg<32){ src=g_H1p; off=((size_t)t*32+kbg)*BAT; }
            else { src=hb2; off=(size_t)(kbg-32)*BAT; }
            cp16(su32(dst+(kbl*64+r)*8+hf*4), src+(off+bg*64+r)*8+hf*4);
        }
    };
    auto mmaC=[&](float acc[2][4][4],int c){
        const unsigned* Au=(const unsigned*)(stg+(c%3)*2048);
#pragma unroll
        for(int kbl=0;kbl<4;kbl++){
            int kbg=kbgOf(c,kbl);
            uint2 x0[2],x1[2];
#pragma unroll
            for(int mt=0;mt<2;mt++){
                int r=wm*32+mt*16+g;
                x0[mt]=*(const uint2*)&Au[(kbl*64+r)*8+tg*2];
                x1[mt]=*(const uint2*)&Au[(kbl*64+r+8)*8+tg*2];
            }
#pragma unroll
            for(int nt=0;nt<4;nt++){
                uint2 bv=Wpk[(kbg*64+nt*16+wn*8+g)*4+tg];
                mma16(acc[0][nt],x0[0].x,x1[0].x,x0[0].y,x1[0].y,bv.x,bv.y);
                mma16(acc[1][nt],x0[1].x,x1[1].x,x0[1].y,x1[1].y,bv.x,bv.y);
            }
        }
    };

    for(int t=0;t<TST;t++){
        // SEC: pre-issue h1 chunk 0 (buf0, outside red region) to hide under poll
        if(SEC){ issueA(t,0); cpc(); }
        if(t>0){
            if(tid<32){
                const volatile unsigned* f=&g_sync[(bg*32+tid)*32];
                unsigned tgt=base+(unsigned)t;
                while(*f<tgt){}
            }
            __threadfence(); __syncthreads();
        }
        if(SEC){ issueA(t,1); cpc(); }
        else { issueA(t,0); cpc(); issueA(t,1); cpc(); }

        float acc[2][4][4];
        if(wg==1){
            if(!SEC){
#pragma unroll
                for(int mt=0;mt<2;mt++) for(int nt=0;nt<4;nt++)
                    for(int q=0;q<4;q++) acc[mt][nt][q]=xzp[mt][nt][q];
                if(t+1<TST) pfxz(t+1);
            } else {
#pragma unroll
                for(int mt=0;mt<2;mt++) for(int nt=0;nt<4;nt++){
                    acc[mt][nt][0]=bz[nt][0]; acc[mt][nt][1]=bz[nt][1];
                    acc[mt][nt][2]=bz[nt][0]; acc[mt][nt][3]=bz[nt][1];
                }
            }
        } else {
#pragma unroll
            for(int m=0;m<2;m++) for(int n=0;n<4;n++)
                for(int q=0;q<4;q++) acc[m][n][q]=0.f;
        }

        for(int c=0;c<C;c++){
            if(c<C-1) cpw<1>(); else cpw<0>();
            barwg(barid);
            if(c+2<C){ issueA(t,c+2); cpc(); }
            mmaC(acc,c);
        }
        barwg(barid);

        if(wg!=0){
            float4* redw=(float4*)(stg+RED);   // 4096 floats = 1024 float4
#pragma unroll
            for(int mt=0;mt<2;mt++)
#pragma unroll
                for(int nt=0;nt<4;nt++){
                    int jj=mt*4+nt;
                    float4 v={acc[mt][nt][0],acc[mt][nt][1],
                              acc[mt][nt][2],acc[mt][nt][3]};
                    redw[wtid*8+((jj+wtid)&7)]=v;
                }
        }
        __syncthreads();
        if(wg==0){
            unsigned* hn = SEC? g_Hb2[(t&1)^1] : g_Hb1[(t&1)^1];
#pragma unroll
            for(int mt=0;mt<2;mt++){
                float hq[2][2];
#pragma unroll
                for(int nt=0;nt<4;nt++){
                    int jj=mt*4+nt;
#pragma unroll
                    for(int ww=1;ww<4;ww++){
                        const float4* redw=(const float4*)(stgb+ww*6144+RED);
                        float4 v=redw[wtid*8+((jj+wtid)&7)];
                        acc[mt][nt][0]+=v.x; acc[mt][nt][1]+=v.y;
                        acc[mt][nt][2]+=v.z; acc[mt][nt][3]+=v.w;
                    }
                }
#pragma unroll
                for(int q=0;q<4;q++){
                    float ig=siga(acc[mt][0][q]);
                    float fg=siga(acc[mt][1][q]);
                    float gv=tanha(acc[mt][2][q]);
                    float og=siga(acc[mt][3][q]);
                    float cc_=fg*cst[mt][q]+ig*gv;
                    cst[mt][q]=cc_;
                    hq[q>>1][q&1]=og*tanha(cc_);
                }
#pragma unroll
                for(int p=0;p<2;p++){
                    int b=bg*64+wm*32+mt*16+p*8+g;
                    int U0=strip*16+wn*8+tg*2;
                    unsigned pv=pk2(hq[p][0],hq[p][1]);
                    if(SEC) *(unsigned*)&g_H2[((size_t)t*BAT+b)*HID+U0]=pv;
                    else g_H1p[(((size_t)t*32+strip)*BAT+b)*8+tg*2+wn]=pv;
                    hn[((size_t)strip*BAT+b)*8+tg*2+wn]=pv;
                }
            }
            barwg(1);
            if(tid==0){
                __threadfence();
                g_sync[(bg*32+strip)*32]=base+(unsigned)(t+1);
            }
        }
    }
}

// ---------------- heads ----------------
__global__ __launch_bounds__(256) void head_k(const __nv_bfloat16* __restrict__ h,
        const float* __restrict__ Wmu, const float* __restrict__ bmu,
        const float* __restrict__ Wsig, const float* __restrict__ bsig,
        float* __restrict__ out){
    int w=threadIdx.x>>5, l=threadIdx.x&31;
    int r=blockIdx.x*8+w;
    const __nv_bfloat16* hr=h+(size_t)r*HID;
    float smu=0.f, ssg=0.f;
    for(int k=l;k<HID;k+=32){
        float hv=__bfloat162float(hr[k]);
        smu+=hv*Wmu[k]; ssg+=hv*Wsig[k];
    }
#pragma unroll
    for(int o=16;o;o>>=1){
        smu+=__shfl_xor_sync(0xFFFFFFFFu,smu,o);
        ssg+=__shfl_xor_sync(0xFFFFFFFFu,ssg,o);
    }
    if(l==0){
        int t=r>>8, b=r&255;
        out[b*TST+t]=smu+bmu[0];
        float x=ssg+bsig[0];
        out[RWS+b*TST+t]=(x>20.f)? x : log1pf(__expf(x));
    }
}

extern "C" void kernel_launch(void* const* d_in, const int* in_sizes, int n_in,
                              void* d_out, int out_size){
    const float* xc  =(const float*)d_in[0];
    const int*   c0  =(const int*  )d_in[1];
    const int*   c1  =(const int*  )d_in[2];
    const float* e0  =(const float*)d_in[3];
    const float* e1  =(const float*)d_in[4];
    const float* Wk1 =(const float*)d_in[5];
    const float* Wr1 =(const float*)d_in[6];
    const float* b1  =(const float*)d_in[7];
    const float* Wk2 =(const float*)d_in[8];
    const float* Wr2 =(const float*)d_in[9];
    const float* b2  =(const float*)d_in[10];
    const float* Wmu =(const float*)d_in[11];
    const float* bmu =(const float*)d_in[12];
    const float* Wsig=(const float*)d_in[13];
    const float* bsig=(const float*)d_in[14];
    float* out=(float*)d_out;

    cudaFuncSetAttribute(lstm_t<8,false>,
        cudaFuncAttributeMaxDynamicSharedMemorySize, 163840);
    cudaFuncSetAttribute(lstm_t<16,true>,
        cudaFuncAttributeMaxDynamicSharedMemorySize, 229376);
    cudaFuncSetAttribute(gemm64, cudaFuncAttributeMaxDynamicSharedMemorySize, 36864);

    void *pX,*pXZ,*pH2,*pW1;
    cudaGetSymbolAddress(&pX,  g_X);
    cudaGetSymbolAddress(&pXZ, g_XZ);
    cudaGetSymbolAddress(&pH2, g_H2);
    cudaGetSymbolAddress(&pW1, g_Wk1p);

    prep_k<<<3072,256>>>(xc,c0,c1,e0,e1,Wk1);
    zero_k<<<1024,256>>>();
    gemm64<<<dim3(32,RWS/64),128,36864>>>((const __nv_bfloat16*)pX,
        (const unsigned*)pW1,b1,(float*)pXZ,64);
    lstm_t<8,false><<<128,512,163840>>>((const float*)pXZ,Wr1,Wr1,b1,0u);
    lstm_t<16,true><<<128,512,229376>>>((const float*)pXZ,Wk2,Wr2,b2,192u);
    head_k<<<RWS/8,256>>>((const __nv_bfloat16*)pH2,Wmu,bmu,Wsig,bsig,out);
    rst_k<<<1,128>>>();
}

// round 13
// speedup vs baseline: 1.0251x; 1.0251x over previous
#include <cuda_runtime.h>
#include <cuda_bf16.h>
#include <cstdint>
#include <cstddef>

#define TST 192
#define BAT 256
#define HID 512
#define G4  2048
#define RWS (TST*BAT)

__device__ __nv_bfloat16 g_X[(size_t)RWS*64];
__device__ float g_XZ[(size_t)RWS*G4];
__device__ unsigned g_H1p[(size_t)TST*32*BAT*8];
__device__ __nv_bfloat16 g_H2[(size_t)RWS*HID];
__device__ unsigned g_Hb1[2][32*BAT*8];
__device__ unsigned g_Hb2[2][32*BAT*8];
__device__ unsigned g_Wk1p[32*G4];
__device__ volatile unsigned g_sy1[128*32];
__device__ volatile unsigned g_sy2[128*32];

__device__ __forceinline__ unsigned pk2(float x, float y){
    __nv_bfloat162 t=__floats2bfloat162_rn(x,y);
    return *(unsigned*)&t;
}
__device__ __forceinline__ void mma16(float* d, unsigned a0,unsigned a1,unsigned a2,
                                      unsigned a3, unsigned b0,unsigned b1){
    asm volatile("mma.sync.aligned.m16n8k16.row.col.f32.bf16.bf16.f32 "
        "{%0,%1,%2,%3}, {%4,%5,%6,%7}, {%8,%9}, {%0,%1,%2,%3};\n"
        : "+f"(d[0]),"+f"(d[1]),"+f"(d[2]),"+f"(d[3])
        : "r"(a0),"r"(a1),"r"(a2),"r"(a3),"r"(b0),"r"(b1));
}
__device__ __forceinline__ unsigned su32(const void* p){
    return (unsigned)__cvta_generic_to_shared(p);
}
__device__ __forceinline__ void cp16(unsigned dst, const void* src){
    asm volatile("cp.async.cg.shared.global [%0], [%1], 16;" :: "r"(dst), "l"(src));
}
__device__ __forceinline__ void cpc(){ asm volatile("cp.async.commit_group;"); }
template<int N> __device__ __forceinline__ void cpw(){
    asm volatile("cp.async.wait_group %0;" :: "n"(N));
}
__device__ __forceinline__ void bw(int id,int n){
    asm volatile("bar.sync %0, %1;" :: "r"(id), "r"(n) : "memory");
}
__device__ __forceinline__ float tanha(float x){
    float r; asm("tanh.approx.f32 %0,%1;" : "=f"(r) : "f"(x)); return r;
}
__device__ __forceinline__ float siga(float x){ return fmaf(tanha(x*0.5f),0.5f,0.5f); }

__global__ void prep_k(const float* __restrict__ xc, const int* __restrict__ c0,
                       const int* __restrict__ c1, const float* __restrict__ e0,
                       const float* __restrict__ e1, const float* __restrict__ Wk1){
    const size_t N1=(size_t)RWS*64, NT=N1+32*G4;
    for(size_t i=(size_t)blockIdx.x*blockDim.x+threadIdx.x; i<NT;
        i+=(size_t)gridDim.x*blockDim.x){
        if(i<N1){
            int r=(int)(i>>6), cc=(int)(i&63), t=r>>8, b=r&255;
            float v=0.f;
            if(cc<8)       v=xc[(b*TST+t)*8+cc];
            else if(cc<40) v=e0[(size_t)c0[b*TST+t]*32+(cc-8)];
            else if(cc<56) v=e1[(size_t)c1[b*TST+t]*16+(cc-40)];
            g_X[i]=__float2bfloat16_rn(v);
        } else {
            size_t j=i-N1; int jr=(int)(j>>11), n=(int)(j&2047);
            float v0=(2*jr<56)?   Wk1[(size_t)(2*jr)*G4+n]   : 0.f;
            float v1=(2*jr+1<56)? Wk1[(size_t)(2*jr+1)*G4+n] : 0.f;
            g_Wk1p[j]=pk2(v0,v1);
        }
    }
}

__global__ void zero_k(){
    int i=blockIdx.x*blockDim.x+threadIdx.x;
    if(i<131072) ((unsigned*)g_Hb1)[i]=0u;
    else if(i<262144) ((unsigned*)g_Hb2)[i-131072]=0u;
}

__global__ void rst_k(){
    int i=threadIdx.x;
    if(i<128){ g_sy1[i*32]=0u; g_sy2[i*32]=0u; }
}

__global__ __launch_bounds__(128) void gemm64(const __nv_bfloat16* __restrict__ A,
        const unsigned* __restrict__ Wp, const float* __restrict__ bias,
        float* __restrict__ C, int K){
    extern __shared__ float sm[];
    const int tid=threadIdx.x, l=tid&31, w=tid>>5, wm=w>>1, wn=w&1;
    const int g=l>>2, tg=l&3;
    const int row0=blockIdx.y*64, col0=blockIdx.x*64;
    float acc[2][4][4];
#pragma unroll
    for(int m=0;m<2;m++) for(int n=0;n<4;n++) for(int q=0;q<4;q++) acc[m][n][q]=0.f;
    const int NC=K>>6;
    auto issue=[&](int c){
        unsigned* Au=(unsigned*)(sm+(c&1)*4608);
        unsigned* Bu=Au+2304;
#pragma unroll
        for(int q=0;q<4;q++){ int e=tid+128*q, r=e>>3, s=e&7;
            cp16(su32(Au+r*36+s*4), A+(size_t)(row0+r)*K + c*64 + s*8); }
#pragma unroll
        for(int q=0;q<4;q++){ int e=tid+128*q, j=e>>4, s=e&15;
            cp16(su32(Bu+j*72+s*4), Wp+(size_t)(c*32+j)*G4 + col0 + s*4); }
    };
    issue(0); cpc();
    for(int c=0;c<NC;c++){
        if(c+1<NC){ issue(c+1); cpc(); cpw<1>(); } else cpw<0>();
        __syncthreads();
        const unsigned* Au=(const unsigned*)(sm+(c&1)*4608);
        const unsigned* Bu=Au+2304;
#pragma unroll
        for(int kb=0;kb<4;kb++){
            unsigned a[2][4];
#pragma unroll
            for(int mt=0;mt<2;mt++){
                int r=wm*32+mt*16+g;
                a[mt][0]=Au[r*36+kb*8+tg];   a[mt][1]=Au[(r+8)*36+kb*8+tg];
                a[mt][2]=Au[r*36+kb*8+tg+4]; a[mt][3]=Au[(r+8)*36+kb*8+tg+4];
            }
#pragma unroll
            for(int nt=0;nt<4;nt++){
                int cc=wn*32+nt*8+g;
                unsigned b0=Bu[(kb*8+tg)*72+cc], b1=Bu[(kb*8+tg+4)*72+cc];
                mma16(acc[0][nt],a[0][0],a[0][1],a[0][2],a[0][3],b0,b1);
                mma16(acc[1][nt],a[1][0],a[1][1],a[1][2],a[1][3],b0,b1);
            }
        }
        __syncthreads();
    }
#pragma unroll
    for(int nt=0;nt<4;nt++){
        int cc=col0+wn*32+nt*8+tg*2;
        float bx=bias[cc], by=bias[cc+1];
#pragma unroll
        for(int mt=0;mt<2;mt++){
            int r=row0+wm*32+mt*16+g;
            float2 v0={acc[mt][nt][0]+bx, acc[mt][nt][1]+by};
            float2 v1={acc[mt][nt][2]+bx, acc[mt][nt][3]+by};
            *(float2*)&C[(size_t)r*G4+cc]=v0;
            *(float2*)&C[(size_t)(r+8)*G4+cc]=v1;
        }
    }
}

// fused: CTAs 0-63 layer1, 64-127 layer2 (lag 1). CTA = 128 rows x 16 units.
// 4 wg = (m rowhalf 64, kk Khalf). SMEM: Wpk 128KB | rings 4x24KB.
__global__ __launch_bounds__(512) void lstm_f(const float* __restrict__ xz,
        const float* __restrict__ Wr1, const float* __restrict__ Wk2,
        const float* __restrict__ Wr2, const float* __restrict__ b2){
    extern __shared__ float sm[];
    uint2* Wpk=(uint2*)sm;
    const int tid=threadIdx.x, l=tid&31, w=tid>>5;
    const int wg=w>>2, m=wg>>1, kk=wg&1, wl=w&3, wm=wl>>1, wn=wl&1;
    const int g=l>>2, tg=l&3, wtid=tid&127;
    const int LY2=blockIdx.x>>6;
    const int idx=blockIdx.x&63, strip=idx&31, bg=idx>>5;
    const int NKB=LY2?64:32, C=LY2?8:4;
    float* ring=sm+32768+wg*6144;
    const int rb=3+wg;

    for(int e=tid;e<NKB*256;e+=512){
        int tg_=e&3, ci=(e>>2)&63, kb=e>>8;
        int nt=ci>>4, wn_=(ci>>3)&1, gg=ci&7;
        int gcol=nt*HID+strip*16+wn_*8+gg;
        const float* W; int kr;
        if(!LY2){ W=Wr1; kr=kb; }
        else if(kb<32){ W=Wk2; kr=kb; }
        else { W=Wr2; kr=kb-32; }
        int k0=kr*16+tg_*2;
        uint2 v;
        v.x=pk2(W[(size_t)k0*G4+gcol],     W[(size_t)(k0+1)*G4+gcol]);
        v.y=pk2(W[(size_t)(k0+8)*G4+gcol], W[(size_t)(k0+9)*G4+gcol]);
        Wpk[e]=v;
    }
    __syncthreads();

    float cst[2][4];
#pragma unroll
    for(int a=0;a<2;a++) for(int q=0;q<4;q++) cst[a][q]=0.f;
    float xzp[2][4][4];
    float bz[4][2];

    auto pfxz=[&](int tt){
        const float* xr=xz+(size_t)tt*BAT*G4;
#pragma unroll
        for(int mt=0;mt<2;mt++)
#pragma unroll
            for(int nt=0;nt<4;nt++){
                int b=bg*128+m*64+wm*32+mt*16+g;
                int cc=nt*HID+strip*16+wn*8+tg*2;
                float2 v0=*(const float2*)&xr[(size_t)b*G4+cc];
                float2 v1=*(const float2*)&xr[(size_t)(b+8)*G4+cc];
                xzp[mt][nt][0]=v0.x; xzp[mt][nt][1]=v0.y;
                xzp[mt][nt][2]=v1.x; xzp[mt][nt][3]=v1.y;
            }
    };
    if(kk==1){
        if(!LY2) pfxz(0);
        else {
#pragma unroll
            for(int nt=0;nt<4;nt++){
                int cc=nt*HID+strip*16+wn*8+tg*2;
                bz[nt][0]=b2[cc]; bz[nt][1]=b2[cc+1];
            }
        }
    }

    auto pollf=[&](volatile unsigned* fl, unsigned tgt){
        if(wtid<64){
            const volatile unsigned* f=&fl[(bg*64+wtid)*32];
            while(*f<tgt){}
        }
        __threadfence();
        bw(rb,128);
    };
    auto issueA=[&](int t,int c){
        float* dst=ring+(c%3)*2048;
#pragma unroll
        for(int q=0;q<4;q++){
            int e=wtid+128*q;
            int kbl=e>>7, rem=e&127, r=rem>>1, hf=rem&1;
            int x=kk*(NKB>>1)+c*4+kbl;
            const unsigned* src; size_t off;
            if(!LY2){ src=g_Hb1[t&1]; off=(size_t)x*BAT; }
            else if(x<32){ src=g_H1p; off=((size_t)t*32+x)*BAT; }
            else { src=g_Hb2[t&1]; off=(size_t)(x-32)*BAT; }
            cp16(su32(dst+(kbl*64+r)*8+hf*4),
                 src+(off+bg*128+m*64+r)*8+hf*4);
        }
    };
    auto mmaC=[&](float acc[2][4][4],int c){
        const unsigned* Au=(const unsigned*)(ring+(c%3)*2048);
#pragma unroll
        for(int kbl=0;kbl<4;kbl++){
            int x=kk*(NKB>>1)+c*4+kbl;
            uint2 x0[2],x1[2];
#pragma unroll
            for(int mt=0;mt<2;mt++){
                int r=wm*32+mt*16+g;
                x0[mt]=*(const uint2*)&Au[(kbl*64+r)*8+tg*2];
                x1[mt]=*(const uint2*)&Au[(kbl*64+r+8)*8+tg*2];
            }
#pragma unroll
            for(int nt=0;nt<4;nt++){
                uint2 bv=Wpk[(x*64+nt*16+wn*8+g)*4+tg];
                mma16(acc[0][nt],x0[0].x,x1[0].x,x0[0].y,x1[0].y,bv.x,bv.y);
                mma16(acc[1][nt],x0[1].x,x1[1].x,x0[1].y,x1[1].y,bv.x,bv.y);
            }
        }
    };

    for(int t=0;t<TST;t++){
        if(!LY2){ if(t>0) pollf(g_sy1,(unsigned)t); }
        else {
            if(kk==0) pollf(g_sy1,(unsigned)(t+1));
            else if(t>0) pollf(g_sy2,(unsigned)t);
        }
        issueA(t,0); cpc(); issueA(t,1); cpc();

        float acc[2][4][4];
        if(kk==1){
            if(!LY2){
#pragma unroll
                for(int mt=0;mt<2;mt++) for(int nt=0;nt<4;nt++)
                    for(int q=0;q<4;q++) acc[mt][nt][q]=xzp[mt][nt][q];
            } else {
#pragma unroll
                for(int mt=0;mt<2;mt++) for(int nt=0;nt<4;nt++){
                    acc[mt][nt][0]=bz[nt][0]; acc[mt][nt][1]=bz[nt][1];
                    acc[mt][nt][2]=bz[nt][0]; acc[mt][nt][3]=bz[nt][1];
                }
            }
        } else {
#pragma unroll
            for(int a=0;a<2;a++) for(int n=0;n<4;n++)
                for(int q=0;q<4;q++) acc[a][n][q]=0.f;
        }

        for(int c=0;c<C;c++){
            if(c<C-1) cpw<1>(); else cpw<0>();
            bw(rb,128);
            if(c+2<C){ issueA(t,c+2); cpc(); }
            mmaC(acc,c);
        }
        bw(rb,128);

        if(kk==1){
            float4* red=(float4*)ring;   // bufs 0+1 = 16KB, all reads done
#pragma unroll
            for(int mt=0;mt<2;mt++)
#pragma unroll
                for(int nt=0;nt<4;nt++){
                    int jj=mt*4+nt;
                    float4 v={acc[mt][nt][0],acc[mt][nt][1],
                              acc[mt][nt][2],acc[mt][nt][3]};
                    red[wtid*8+((jj+wtid)&7)]=v;
                }
        }
        bw(1+m,256);
        if(kk==0){
            const float4* red=(const float4*)(sm+32768+(m*2+1)*6144);
#pragma unroll
            for(int mt=0;mt<2;mt++)
#pragma unroll
                for(int nt=0;nt<4;nt++){
                    int jj=mt*4+nt;
                    float4 v=red[wtid*8+((jj+wtid)&7)];
                    acc[mt][nt][0]+=v.x; acc[mt][nt][1]+=v.y;
                    acc[mt][nt][2]+=v.z; acc[mt][nt][3]+=v.w;
                }
        }
        bw(7+m,256);   // kk=1 ring reuse safe after this

        if(kk==0){
#pragma unroll
            for(int mt=0;mt<2;mt++){
                float hq[2][2];
#pragma unroll
                for(int q=0;q<4;q++){
                    float ig=siga(acc[mt][0][q]);
                    float fg=siga(acc[mt][1][q]);
                    float gv=tanha(acc[mt][2][q]);
                    float og=siga(acc[mt][3][q]);
                    float cc_=fg*cst[mt][q]+ig*gv;
                    cst[mt][q]=cc_;
                    hq[q>>1][q&1]=og*tanha(cc_);
                }
#pragma unroll
                for(int p=0;p<2;p++){
                    int b=bg*128+m*64+wm*32+mt*16+p*8+g;
                    unsigned pv=pk2(hq[p][0],hq[p][1]);
                    if(LY2){
                        int U0=strip*16+wn*8+tg*2;
                        *(unsigned*)&g_H2[((size_t)t*BAT+b)*HID+U0]=pv;
                        g_Hb2[(t&1)^1][((size_t)strip*BAT+b)*8+tg*2+wn]=pv;
                    } else {
                        g_H1p[(((size_t)t*32+strip)*BAT+b)*8+tg*2+wn]=pv;
                        g_Hb1[(t&1)^1][((size_t)strip*BAT+b)*8+tg*2+wn]=pv;
                    }
                }
            }
            bw(rb,128);   // all wg threads' stores done
            if(wtid==0){
                __threadfence();
                if(LY2) g_sy2[(bg*64+strip*2+m)*32]=(unsigned)(t+1);
                else    g_sy1[(bg*64+strip*2+m)*32]=(unsigned)(t+1);
            }
        } else {
            if(!LY2 && t+1<TST) pfxz(t+1);
        }
    }
}

__global__ __launch_bounds__(256) void head_k(const __nv_bfloat16* __restrict__ h,
        const float* __restrict__ Wmu, const float* __restrict__ bmu,
        const float* __restrict__ Wsig, const float* __restrict__ bsig,
        float* __restrict__ out){
    int w=threadIdx.x>>5, l=threadIdx.x&31;
    int r=blockIdx.x*8+w;
    const __nv_bfloat16* hr=h+(size_t)r*HID;
    float smu=0.f, ssg=0.f;
    for(int k=l;k<HID;k+=32){
        float hv=__bfloat162float(hr[k]);
        smu+=hv*Wmu[k]; ssg+=hv*Wsig[k];
    }
#pragma unroll
    for(int o=16;o;o>>=1){
        smu+=__shfl_xor_sync(0xFFFFFFFFu,smu,o);
        ssg+=__shfl_xor_sync(0xFFFFFFFFu,ssg,o);
    }
    if(l==0){
        int t=r>>8, b=r&255;
        out[b*TST+t]=smu+bmu[0];
        float x=ssg+bsig[0];
        out[RWS+b*TST+t]=(x>20.f)? x : log1pf(__expf(x));
    }
}

extern "C" void kernel_launch(void* const* d_in, const int* in_sizes, int n_in,
                              void* d_out, int out_size){
    const float* xc  =(const float*)d_in[0];
    const int*   c0  =(const int*  )d_in[1];
    const int*   c1  =(const int*  )d_in[2];
    const float* e0  =(const float*)d_in[3];
    const float* e1  =(const float*)d_in[4];
    const float* Wk1 =(const float*)d_in[5];
    const float* Wr1 =(const float*)d_in[6];
    const float* b1  =(const float*)d_in[7];
    const float* Wk2 =(const float*)d_in[8];
    const float* Wr2 =(const float*)d_in[9];
    const float* b2  =(const float*)d_in[10];
    const float* Wmu =(const float*)d_in[11];
    const float* bmu =(const float*)d_in[12];
    const float* Wsig=(const float*)d_in[13];
    const float* bsig=(const float*)d_in[14];
    float* out=(float*)d_out;

    cudaFuncSetAttribute(lstm_f, cudaFuncAttributeMaxDynamicSharedMemorySize, 229376);
    cudaFuncSetAttribute(gemm64, cudaFuncAttributeMaxDynamicSharedMemorySize, 36864);

    void *pX,*pXZ,*pH2,*pW1;
    cudaGetSymbolAddress(&pX,  g_X);
    cudaGetSymbolAddress(&pXZ, g_XZ);
    cudaGetSymbolAddress(&pH2, g_H2);
    cudaGetSymbolAddress(&pW1, g_Wk1p);

    prep_k<<<3072,256>>>(xc,c0,c1,e0,e1,Wk1);
    zero_k<<<1024,256>>>();
    gemm64<<<dim3(32,RWS/64),128,36864>>>((const __nv_bfloat16*)pX,
        (const unsigned*)pW1,b1,(float*)pXZ,64);
    lstm_f<<<128,512,229376>>>((const float*)pXZ,Wr1,Wk2,Wr2,b2);
    head_k<<<RWS/8,256>>>((const __nv_bfloat16*)pH2,Wmu,bmu,Wsig,bsig,out);
    rst_k<<<1,128>>>();
}

// round 14
// speedup vs baseline: 1.0743x; 1.0480x over previous
#include <cuda_runtime.h>
#include <cuda_bf16.h>
#include <cstdint>
#include <cstddef>

#define TST 192
#define BAT 256
#define HID 512
#define G4  2048
#define RWS (TST*BAT)

__device__ __nv_bfloat16 g_X[(size_t)RWS*64];
__device__ float g_XZ[(size_t)RWS*G4];
__device__ unsigned g_H1p[(size_t)TST*32*BAT*8];
__device__ __nv_bfloat16 g_H2[(size_t)RWS*HID];
__device__ unsigned g_Hb1[2][32*BAT*8];
__device__ unsigned g_Hb2[2][32*BAT*8];
__device__ unsigned g_Wk1p[32*G4];
__device__ volatile unsigned g_sy1[128*32];
__device__ volatile unsigned g_sy2[128*32];

__device__ __forceinline__ unsigned pk2(float x, float y){
    __nv_bfloat162 t=__floats2bfloat162_rn(x,y);
    return *(unsigned*)&t;
}
__device__ __forceinline__ void mma16(float* d, unsigned a0,unsigned a1,unsigned a2,
                                      unsigned a3, unsigned b0,unsigned b1){
    asm volatile("mma.sync.aligned.m16n8k16.row.col.f32.bf16.bf16.f32 "
        "{%0,%1,%2,%3}, {%4,%5,%6,%7}, {%8,%9}, {%0,%1,%2,%3};\n"
        : "+f"(d[0]),"+f"(d[1]),"+f"(d[2]),"+f"(d[3])
        : "r"(a0),"r"(a1),"r"(a2),"r"(a3),"r"(b0),"r"(b1));
}
__device__ __forceinline__ unsigned su32(const void* p){
    return (unsigned)__cvta_generic_to_shared(p);
}
__device__ __forceinline__ void cp16(unsigned dst, const void* src){
    asm volatile("cp.async.cg.shared.global [%0], [%1], 16;" :: "r"(dst), "l"(src));
}
__device__ __forceinline__ void cpc(){ asm volatile("cp.async.commit_group;"); }
template<int N> __device__ __forceinline__ void cpw(){
    asm volatile("cp.async.wait_group %0;" :: "n"(N));
}
__device__ __forceinline__ void bw(int id,int n){
    asm volatile("bar.sync %0, %1;" :: "r"(id), "r"(n) : "memory");
}
__device__ __forceinline__ float tanha(float x){
    float r; asm("tanh.approx.f32 %0,%1;" : "=f"(r) : "f"(x)); return r;
}
__device__ __forceinline__ float siga(float x){ return fmaf(tanha(x*0.5f),0.5f,0.5f); }

__global__ void prep_k(const float* __restrict__ xc, const int* __restrict__ c0,
                       const int* __restrict__ c1, const float* __restrict__ e0,
                       const float* __restrict__ e1, const float* __restrict__ Wk1){
    const size_t N1=(size_t)RWS*64, NT=N1+32*G4;
    for(size_t i=(size_t)blockIdx.x*blockDim.x+threadIdx.x; i<NT;
        i+=(size_t)gridDim.x*blockDim.x){
        if(i<N1){
            int r=(int)(i>>6), cc=(int)(i&63), t=r>>8, b=r&255;
            float v=0.f;
            if(cc<8)       v=xc[(b*TST+t)*8+cc];
            else if(cc<40) v=e0[(size_t)c0[b*TST+t]*32+(cc-8)];
            else if(cc<56) v=e1[(size_t)c1[b*TST+t]*16+(cc-40)];
            g_X[i]=__float2bfloat16_rn(v);
        } else {
            size_t j=i-N1; int jr=(int)(j>>11), n=(int)(j&2047);
            float v0=(2*jr<56)?   Wk1[(size_t)(2*jr)*G4+n]   : 0.f;
            float v1=(2*jr+1<56)? Wk1[(size_t)(2*jr+1)*G4+n] : 0.f;
            g_Wk1p[j]=pk2(v0,v1);
        }
    }
}

__global__ void zero_k(){
    int i=blockIdx.x*blockDim.x+threadIdx.x;
    if(i<131072) ((unsigned*)g_Hb1)[i]=0u;
    else if(i<262144) ((unsigned*)g_Hb2)[i-131072]=0u;
}

__global__ void rst_k(){
    int i=threadIdx.x;
    if(i<128){ g_sy1[i*32]=0u; g_sy2[i*32]=0u; }
}

__global__ __launch_bounds__(128) void gemm64(const __nv_bfloat16* __restrict__ A,
        const unsigned* __restrict__ Wp, const float* __restrict__ bias,
        float* __restrict__ C, int K){
    extern __shared__ float sm[];
    const int tid=threadIdx.x, l=tid&31, w=tid>>5, wm=w>>1, wn=w&1;
    const int g=l>>2, tg=l&3;
    const int row0=blockIdx.y*64, col0=blockIdx.x*64;
    float acc[2][4][4];
#pragma unroll
    for(int m=0;m<2;m++) for(int n=0;n<4;n++) for(int q=0;q<4;q++) acc[m][n][q]=0.f;
    const int NC=K>>6;
    auto issue=[&](int c){
        unsigned* Au=(unsigned*)(sm+(c&1)*4608);
        unsigned* Bu=Au+2304;
#pragma unroll
        for(int q=0;q<4;q++){ int e=tid+128*q, r=e>>3, s=e&7;
            cp16(su32(Au+r*36+s*4), A+(size_t)(row0+r)*K + c*64 + s*8); }
#pragma unroll
        for(int q=0;q<4;q++){ int e=tid+128*q, j=e>>4, s=e&15;
            cp16(su32(Bu+j*72+s*4), Wp+(size_t)(c*32+j)*G4 + col0 + s*4); }
    };
    issue(0); cpc();
    for(int c=0;c<NC;c++){
        if(c+1<NC){ issue(c+1); cpc(); cpw<1>(); } else cpw<0>();
        __syncthreads();
        const unsigned* Au=(const unsigned*)(sm+(c&1)*4608);
        const unsigned* Bu=Au+2304;
#pragma unroll
        for(int kb=0;kb<4;kb++){
            unsigned a[2][4];
#pragma unroll
            for(int mt=0;mt<2;mt++){
                int r=wm*32+mt*16+g;
                a[mt][0]=Au[r*36+kb*8+tg];   a[mt][1]=Au[(r+8)*36+kb*8+tg];
                a[mt][2]=Au[r*36+kb*8+tg+4]; a[mt][3]=Au[(r+8)*36+kb*8+tg+4];
            }
#pragma unroll
            for(int nt=0;nt<4;nt++){
                int cc=wn*32+nt*8+g;
                unsigned b0=Bu[(kb*8+tg)*72+cc], b1=Bu[(kb*8+tg+4)*72+cc];
                mma16(acc[0][nt],a[0][0],a[0][1],a[0][2],a[0][3],b0,b1);
                mma16(acc[1][nt],a[1][0],a[1][1],a[1][2],a[1][3],b0,b1);
            }
        }
        __syncthreads();
    }
#pragma unroll
    for(int nt=0;nt<4;nt++){
        int cc=col0+wn*32+nt*8+tg*2;
        float bx=bias[cc], by=bias[cc+1];
#pragma unroll
        for(int mt=0;mt<2;mt++){
            int r=row0+wm*32+mt*16+g;
            float2 v0={acc[mt][nt][0]+bx, acc[mt][nt][1]+by};
            float2 v1={acc[mt][nt][2]+bx, acc[mt][nt][3]+by};
            *(float2*)&C[(size_t)r*G4+cc]=v0;
            *(float2*)&C[(size_t)(r+8)*G4+cc]=v1;
        }
    }
}

// fused: CTAs 0-63 layer1, 64-127 layer2 (lag 1). CTA = 128 rows x 16 units.
// 4 wg = (m rowhalf, kk Khalf). L2 chunk order: h1,h1,h2,h2 per wg; flag2 poll at c==2.
__global__ __launch_bounds__(512) void lstm_f(const float* __restrict__ xz,
        const float* __restrict__ Wr1, const float* __restrict__ Wk2,
        const float* __restrict__ Wr2, const float* __restrict__ b2){
    extern __shared__ float sm[];
    uint2* Wpk=(uint2*)sm;
    const int tid=threadIdx.x, l=tid&31, w=tid>>5;
    const int wg=w>>2, m=wg>>1, kk=wg&1, wl=w&3, wm=wl>>1, wn=wl&1;
    const int g=l>>2, tg=l&3, wtid=tid&127;
    const int LY2=blockIdx.x>>6;
    const int idx=blockIdx.x&63, strip=idx&31, bg=idx>>5;
    const int NKB=LY2?64:32, C=LY2?8:4;
    float* ring=sm+32768+wg*6144;
    const int rb=3+wg;

    for(int e=tid;e<NKB*256;e+=512){
        int tg_=e&3, ci=(e>>2)&63, kb=e>>8;
        int nt=ci>>4, wn_=(ci>>3)&1, gg=ci&7;
        int gcol=nt*HID+strip*16+wn_*8+gg;
        const float* W; int kr;
        if(!LY2){ W=Wr1; kr=kb; }
        else if(kb<32){ W=Wk2; kr=kb; }
        else { W=Wr2; kr=kb-32; }
        int k0=kr*16+tg_*2;
        uint2 v;
        v.x=pk2(W[(size_t)k0*G4+gcol],     W[(size_t)(k0+1)*G4+gcol]);
        v.y=pk2(W[(size_t)(k0+8)*G4+gcol], W[(size_t)(k0+9)*G4+gcol]);
        Wpk[e]=v;
    }
    __syncthreads();

    float cst[2][4];
#pragma unroll
    for(int a=0;a<2;a++) for(int q=0;q<4;q++) cst[a][q]=0.f;
    float xzp[2][4][4];
    float bz[4][2];

    auto pfxz=[&](int tt){
        const float* xr=xz+(size_t)tt*BAT*G4;
#pragma unroll
        for(int mt=0;mt<2;mt++)
#pragma unroll
            for(int nt=0;nt<4;nt++){
                int b=bg*128+m*64+wm*32+mt*16+g;
                int cc=nt*HID+strip*16+wn*8+tg*2;
                float2 v0=*(const float2*)&xr[(size_t)b*G4+cc];
                float2 v1=*(const float2*)&xr[(size_t)(b+8)*G4+cc];
                xzp[mt][nt][0]=v0.x; xzp[mt][nt][1]=v0.y;
                xzp[mt][nt][2]=v1.x; xzp[mt][nt][3]=v1.y;
            }
    };
    if(kk==1){
        if(!LY2) pfxz(0);
        else {
#pragma unroll
            for(int nt=0;nt<4;nt++){
                int cc=nt*HID+strip*16+wn*8+tg*2;
                bz[nt][0]=b2[cc]; bz[nt][1]=b2[cc+1];
            }
        }
    }

    auto pollf=[&](volatile unsigned* fl, unsigned tgt){
        if(wtid<64){
            const volatile unsigned* f=&fl[(bg*64+wtid)*32];
            while(*f<tgt){}
        }
        __threadfence();
        bw(rb,128);
    };
    // L2 chunk -> kb block: c<4 -> h1 [kk*16+c*4+kbl], c>=4 -> h2 [32+kk*16+(c-4)*4+kbl]
    auto xOf=[&](int c,int kbl){
        if(!LY2) return kk*16+c*4+kbl;
        return (c<4)? kk*16+c*4+kbl : 32+kk*16+(c-4)*4+kbl;
    };
    auto issueA=[&](int t,int c){
        float* dst=ring+(c%3)*2048;
#pragma unroll
        for(int q=0;q<4;q++){
            int e=wtid+128*q;
            int kbl=e>>7, rem=e&127, r=rem>>1, hf=rem&1;
            int x=xOf(c,kbl);
            const unsigned* src; size_t off;
            if(!LY2){ src=g_Hb1[t&1]; off=(size_t)x*BAT; }
            else if(x<32){ src=g_H1p; off=((size_t)t*32+x)*BAT; }
            else { src=g_Hb2[t&1]; off=(size_t)(x-32)*BAT; }
            cp16(su32(dst+(kbl*64+r)*8+hf*4),
                 src+(off+bg*128+m*64+r)*8+hf*4);
        }
    };
    auto mmaC=[&](float acc[2][4][4],int c){
        const unsigned* Au=(const unsigned*)(ring+(c%3)*2048);
#pragma unroll
        for(int kbl=0;kbl<4;kbl++){
            int x=xOf(c,kbl);
            uint2 x0[2],x1[2];
#pragma unroll
            for(int mt=0;mt<2;mt++){
                int r=wm*32+mt*16+g;
                x0[mt]=*(const uint2*)&Au[(kbl*64+r)*8+tg*2];
                x1[mt]=*(const uint2*)&Au[(kbl*64+r+8)*8+tg*2];
            }
#pragma unroll
            for(int nt=0;nt<4;nt++){
                uint2 bv=Wpk[(x*64+nt*16+wn*8+g)*4+tg];
                mma16(acc[0][nt],x0[0].x,x1[0].x,x0[0].y,x1[0].y,bv.x,bv.y);
                mma16(acc[1][nt],x0[1].x,x1[1].x,x0[1].y,x1[1].y,bv.x,bv.y);
            }
        }
    };

    for(int t=0;t<TST;t++){
        if(!LY2){ if(t>0) pollf(g_sy1,(unsigned)t); }
        else pollf(g_sy1,(unsigned)(t+1));   // h1(t) ready (L1 leads; short wait)
        issueA(t,0); cpc(); issueA(t,1); cpc();

        float acc[2][4][4];
        if(kk==1){
            if(!LY2){
#pragma unroll
                for(int mt=0;mt<2;mt++) for(int nt=0;nt<4;nt++)
                    for(int q=0;q<4;q++) acc[mt][nt][q]=xzp[mt][nt][q];
            } else {
#pragma unroll
                for(int mt=0;mt<2;mt++) for(int nt=0;nt<4;nt++){
                    acc[mt][nt][0]=bz[nt][0]; acc[mt][nt][1]=bz[nt][1];
                    acc[mt][nt][2]=bz[nt][0]; acc[mt][nt][3]=bz[nt][1];
                }
            }
        } else {
#pragma unroll
            for(int a=0;a<2;a++) for(int n=0;n<4;n++)
                for(int q=0;q<4;q++) acc[a][n][q]=0.f;
        }

        for(int c=0;c<C;c++){
            if(LY2 && c==2) pollf(g_sy2,(unsigned)t);  // hidden behind 2 h1 chunks
            if(c<C-1) cpw<1>(); else cpw<0>();
            bw(rb,128);
            if(c+2<C){ issueA(t,c+2); cpc(); }
            mmaC(acc,c);
        }
        bw(rb,128);

        if(kk==1){
            float4* red=(float4*)ring;
#pragma unroll
            for(int mt=0;mt<2;mt++)
#pragma unroll
                for(int nt=0;nt<4;nt++){
                    int jj=mt*4+nt;
                    float4 v={acc[mt][nt][0],acc[mt][nt][1],
                              acc[mt][nt][2],acc[mt][nt][3]};
                    red[wtid*8+((jj+wtid)&7)]=v;
                }
        }
        bw(1+m,256);
        if(kk==0){
            const float4* red=(const float4*)(sm+32768+(m*2+1)*6144);
#pragma unroll
            for(int mt=0;mt<2;mt++)
#pragma unroll
                for(int nt=0;nt<4;nt++){
                    int jj=mt*4+nt;
                    float4 v=red[wtid*8+((jj+wtid)&7)];
                    acc[mt][nt][0]+=v.x; acc[mt][nt][1]+=v.y;
                    acc[mt][nt][2]+=v.z; acc[mt][nt][3]+=v.w;
                }
        }
        bw(7+m,256);

        if(kk==0){
#pragma unroll
            for(int mt=0;mt<2;mt++){
                float hq[2][2];
#pragma unroll
                for(int q=0;q<4;q++){
                    float ig=siga(acc[mt][0][q]);
                    float fg=siga(acc[mt][1][q]);
                    float gv=tanha(acc[mt][2][q]);
                    float og=siga(acc[mt][3][q]);
                    float cc_=fg*cst[mt][q]+ig*gv;
                    cst[mt][q]=cc_;
                    hq[q>>1][q&1]=og*tanha(cc_);
                }
#pragma unroll
                for(int p=0;p<2;p++){
                    int b=bg*128+m*64+wm*32+mt*16+p*8+g;
                    unsigned pv=pk2(hq[p][0],hq[p][1]);
                    if(LY2){
                        int U0=strip*16+wn*8+tg*2;
                        *(unsigned*)&g_H2[((size_t)t*BAT+b)*HID+U0]=pv;
                        g_Hb2[(t&1)^1][((size_t)strip*BAT+b)*8+tg*2+wn]=pv;
                    } else {
                        g_H1p[(((size_t)t*32+strip)*BAT+b)*8+tg*2+wn]=pv;
                        g_Hb1[(t&1)^1][((size_t)strip*BAT+b)*8+tg*2+wn]=pv;
                    }
                }
            }
            bw(rb,128);
            if(wtid==0){
                __threadfence();
                if(LY2) g_sy2[(bg*64+strip*2+m)*32]=(unsigned)(t+1);
                else    g_sy1[(bg*64+strip*2+m)*32]=(unsigned)(t+1);
            }
        } else {
            if(!LY2 && t+1<TST) pfxz(t+1);
        }
    }
}

__global__ __launch_bounds__(256) void head_k(const __nv_bfloat16* __restrict__ h,
        const float* __restrict__ Wmu, const float* __restrict__ bmu,
        const float* __restrict__ Wsig, const float* __restrict__ bsig,
        float* __restrict__ out){
    int w=threadIdx.x>>5, l=threadIdx.x&31;
    int r=blockIdx.x*8+w;
    const __nv_bfloat16* hr=h+(size_t)r*HID;
    float smu=0.f, ssg=0.f;
    for(int k=l;k<HID;k+=32){
        float hv=__bfloat162float(hr[k]);
        smu+=hv*Wmu[k]; ssg+=hv*Wsig[k];
    }
#pragma unroll
    for(int o=16;o;o>>=1){
        smu+=__shfl_xor_sync(0xFFFFFFFFu,smu,o);
        ssg+=__shfl_xor_sync(0xFFFFFFFFu,ssg,o);
    }
    if(l==0){
        int t=r>>8, b=r&255;
        out[b*TST+t]=smu+bmu[0];
        float x=ssg+bsig[0];
        out[RWS+b*TST+t]=(x>20.f)? x : log1pf(__expf(x));
    }
}

extern "C" void kernel_launch(void* const* d_in, const int* in_sizes, int n_in,
                              void* d_out, int out_size){
    const float* xc  =(const float*)d_in[0];
    const int*   c0  =(const int*  )d_in[1];
    const int*   c1  =(const int*  )d_in[2];
    const float* e0  =(const float*)d_in[3];
    const float* e1  =(const float*)d_in[4];
    const float* Wk1 =(const float*)d_in[5];
    const float* Wr1 =(const float*)d_in[6];
    const float* b1  =(const float*)d_in[7];
    const float* Wk2 =(const float*)d_in[8];
    const float* Wr2 =(const float*)d_in[9];
    const float* b2  =(const float*)d_in[10];
    const float* Wmu =(const float*)d_in[11];
    const float* bmu =(const float*)d_in[12];
    const float* Wsig=(const float*)d_in[13];
    const float* bsig=(const float*)d_in[14];
    float* out=(float*)d_out;

    cudaFuncSetAttribute(lstm_f, cudaFuncAttributeMaxDynamicSharedMemorySize, 229376);
    cudaFuncSetAttribute(gemm64, cudaFuncAttributeMaxDynamicSharedMemorySize, 36864);

    void *pX,*pXZ,*pH2,*pW1;
    cudaGetSymbolAddress(&pX,  g_X);
    cudaGetSymbolAddress(&pXZ, g_XZ);
    cudaGetSymbolAddress(&pH2, g_H2);
    cudaGetSymbolAddress(&pW1, g_Wk1p);

    prep_k<<<3072,256>>>(xc,c0,c1,e0,e1,Wk1);
    zero_k<<<1024,256>>>();
    gemm64<<<dim3(32,RWS/64),128,36864>>>((const __nv_bfloat16*)pX,
        (const unsigned*)pW1,b1,(float*)pXZ,64);
    lstm_f<<<128,512,229376>>>((const float*)pXZ,Wr1,Wk2,Wr2,b2);
    head_k<<<RWS/8,256>>>((const __nv_bfloat16*)pH2,Wmu,bmu,Wsig,bsig,out);
    rst_k<<<1,128>>>();
}